// round 2
// baseline (speedup 1.0000x reference)
#include <cuda_runtime.h>
#include <math.h>

// Problem shapes (fixed by the reference)
#define Bsz 4
#define Nn  512
#define Kk  128
#define Ee  768

static constexpr size_t EF_ELEMS    = (size_t)Bsz * Nn * Nn * Kk;   // 134,217,728
static constexpr size_t MERGE_ELEMS = (size_t)Bsz * Nn * Ee;        //   1,572,864
static constexpr size_t MERGE_OFF   = EF_ELEMS;
static constexpr size_t DP_OFF      = EF_ELEMS + MERGE_ELEMS;

// Scratch for sum over j of edge_feature: [B*N, K]  (1 MB, static device array)
__device__ float g_sum[(size_t)Bsz * Nn * Kk];

// Mask dtype modes: 0 = uint8, 1 = int32, 2 = float32
__device__ int g_mode_pad;
__device__ int g_mode_node;

// ---------------------------------------------------------------------------
// Detector: classify bool-mask buffer dtype from byte patterns.
// int32 0/1 words -> high 3 bytes always zero. float32 0/1.0f words are
// {0, 0x3F800000}. uint8 0/1 bytes produce nonzero unaligned bytes with
// overwhelming probability. Scans exactly 2048 bytes (= min possible size).
// ---------------------------------------------------------------------------
__global__ void detect_masks(const unsigned int* __restrict__ pad,
                             const unsigned int* __restrict__ node)
{
    __shared__ unsigned int hi_or[2], bad_f[2];
    const int t = threadIdx.x;              // 128 threads
    if (t < 2) { hi_or[t] = 0u; bad_f[t] = 0u; }
    __syncthreads();

    const unsigned int* bufs[2] = { pad, node };
    for (int m = 0; m < 2; m++) {
        unsigned int h = 0u, bf = 0u;
        for (int w = t; w < 512; w += 128) {   // 512 words = 2048 bytes
            unsigned int v = bufs[m][w];
            h |= (v & 0xFFFFFF00u);
            if (v != 0u && v != 0x3F800000u) bf = 1u;
        }
        atomicOr(&hi_or[m], h);
        atomicOr(&bad_f[m], bf);
    }
    __syncthreads();
    if (t == 0) {
        g_mode_pad  = (hi_or[0] == 0u) ? 1 : (bad_f[0] == 0u ? 2 : 0);
        g_mode_node = (hi_or[1] == 0u) ? 1 : (bad_f[1] == 0u ? 2 : 0);
    }
}

__device__ __forceinline__ bool mget(const void* p, int idx, int mode)
{
    if (mode == 1) return ((const int*)p)[idx] != 0;
    if (mode == 2) return ((const float*)p)[idx] != 0.0f;
    return ((const unsigned char*)p)[idx] != 0;
}

// ---------------------------------------------------------------------------
// Kernel 1: per (b,i) block. Computes delta_pos, edge_feature (streamed),
// and the j-reduction into g_sum.
// ---------------------------------------------------------------------------
__global__ __launch_bounds__(128) void edge_kernel(
    const float* __restrict__ pos,
    const float* __restrict__ means,
    const float* __restrict__ stds,
    const float* __restrict__ mul_w,
    const float* __restrict__ bias_w,
    const int*   __restrict__ nte,
    const void*  __restrict__ pad_mask,
    const void*  __restrict__ node_mask,
    float* __restrict__ out)
{
    const int bi  = blockIdx.x;       // b*512 + i
    const int b   = bi >> 9;
    const int tid = threadIdx.x;      // 0..127

    __shared__ float sx[Nn];          // x = mul*dist + bias per j
    __shared__ float spm[Nn];         // 0 if padding_mask[b,j] else 1
    __shared__ float red[4][Kk];      // cross-j_sub partial sums

    const int mp = g_mode_pad;
    const int mn = g_mode_node;

    const float pix = pos[(size_t)bi * 3 + 0];
    const float piy = pos[(size_t)bi * 3 + 1];
    const float piz = pos[(size_t)bi * 3 + 2];
    const bool  nmi = mget(node_mask, bi, mn);

    // ---- Phase 1: per-j scalars + delta_pos output ----
    for (int j = tid; j < Nn; j += 128) {
        const size_t pj = ((size_t)b * Nn + j) * 3;
        float dx = pos[pj + 0] - pix;
        float dy = pos[pj + 1] - piy;
        float dz = pos[pj + 2] - piz;
        float d2 = dx * dx + dy * dy + dz * dz;
        float dist = (d2 > 0.0f) ? sqrtf(d2) : 0.0f;
        float inv  = 1.0f / (dist + 1e-5f);

        size_t dpo = DP_OFF + ((size_t)bi * Nn + j) * 3;
        out[dpo + 0] = dx * inv;
        out[dpo + 1] = dy * inv;
        out[dpo + 2] = dz * inv;

        size_t eo = ((size_t)bi * Nn + j) * 2;
        int et0 = nte[eo + 0];
        int et1 = nte[eo + 1];
        if (nmi)                        et0 = 0;
        if (mget(node_mask, b * Nn + j, mn)) et1 = 0;

        float mul  = mul_w[et0]  + mul_w[et1];
        float bias = bias_w[et0] + bias_w[et1];
        sx[j]  = fmaf(mul, dist, bias);
        spm[j] = mget(pad_mask, b * Nn + j, mp) ? 0.0f : 1.0f;
    }
    __syncthreads();

    // ---- Phase 2: gaussian basis, streamed stores, j-sum ----
    const int jsub = tid >> 5;            // 0..3
    const int k4   = (tid & 31) * 4;      // this thread's 4 k-values

    float mm[4], is[4], cf[4];
    #pragma unroll
    for (int q = 0; q < 4; q++) {
        float s = fabsf(stds[k4 + q]) + 0.01f;
        is[q] = 1.0f / s;
        mm[q] = means[k4 + q];
        cf[q] = 1.0f / (2.5066268f * s);  // sqrt(2*3.14159) = 2.5066268
    }

    float acc0 = 0.f, acc1 = 0.f, acc2 = 0.f, acc3 = 0.f;
    const size_t base = (size_t)bi * Nn * Kk;

    #pragma unroll 4
    for (int jb = 0; jb < Nn; jb += 4) {
        const int j = jb + jsub;
        const float x  = sx[j];    // broadcast within warp
        const float pm = spm[j];

        float t0 = (x - mm[0]) * is[0];
        float t1 = (x - mm[1]) * is[1];
        float t2 = (x - mm[2]) * is[2];
        float t3 = (x - mm[3]) * is[3];

        float4 v;
        v.x = pm * cf[0] * __expf(-0.5f * t0 * t0);
        v.y = pm * cf[1] * __expf(-0.5f * t1 * t1);
        v.z = pm * cf[2] * __expf(-0.5f * t2 * t2);
        v.w = pm * cf[3] * __expf(-0.5f * t3 * t3);

        acc0 += v.x; acc1 += v.y; acc2 += v.z; acc3 += v.w;

        // Streaming (evict-first) 16B coalesced store of edge_feature
        __stcs(reinterpret_cast<float4*>(out + base + (size_t)j * Kk + k4), v);
    }

    red[jsub][k4 + 0] = acc0;
    red[jsub][k4 + 1] = acc1;
    red[jsub][k4 + 2] = acc2;
    red[jsub][k4 + 3] = acc3;
    __syncthreads();

    // tid indexes k (blockDim == Kk == 128)
    {
        const int k = tid;
        float s = red[0][k] + red[1][k] + red[2][k] + red[3][k];
        g_sum[(size_t)bi * Kk + k] = s;
    }
}

// ---------------------------------------------------------------------------
// Kernel 2: merge = g_sum @ proj_w^T + proj_b, masked.
// M=2048, N=768, K=128. BM=32 rows, grid.y splits N into halves of 384.
// ---------------------------------------------------------------------------
#define DOT4ACC(accv, av, bv) \
    accv = fmaf((av).x, (bv).x, fmaf((av).y, (bv).y, fmaf((av).z, (bv).z, fmaf((av).w, (bv).w, accv))))

__global__ __launch_bounds__(256) void merge_kernel(
    const float* __restrict__ proj_w,
    const float* __restrict__ proj_b,
    const void* __restrict__ pad_mask,
    const void* __restrict__ node_mask,
    float* __restrict__ out)
{
    __shared__ float As[32][132];   // padded, 16B-aligned rows
    __shared__ float Bs[64][132];

    const int tid  = threadIdx.x;
    const int row0 = blockIdx.x * 32;       // 64 blocks in x
    const int e0   = blockIdx.y * 384;      // 2 blocks in y

    const int mp = g_mode_pad;
    const int mn = g_mode_node;

    for (int idx = tid; idx < 32 * 128; idx += 256)
        As[idx >> 7][idx & 127] = g_sum[(size_t)row0 * 128 + idx];

    const int rg = tid >> 5;   // 0..7 -> rows rg*4 .. rg*4+3
    const int eg = tid & 31;   // e within chunk: eg and eg+32

    float bmask[4];
    #pragma unroll
    for (int r = 0; r < 4; r++) {
        int grow = row0 + rg * 4 + r;
        bmask[r] = (mget(pad_mask, grow, mp) || mget(node_mask, grow, mn))
                       ? 0.0f : 1.0f;
    }

    for (int c = 0; c < 6; c++) {           // 6 chunks of 64 e-columns
        __syncthreads();
        const float* pw = proj_w + (size_t)(e0 + c * 64) * 128;
        for (int idx = tid; idx < 64 * 128; idx += 256)
            Bs[idx >> 7][idx & 127] = pw[idx];
        __syncthreads();

        float acc[4][2] = {};
        #pragma unroll
        for (int kb = 0; kb < 128; kb += 4) {
            float4 a0 = *(const float4*)&As[rg * 4 + 0][kb];
            float4 a1 = *(const float4*)&As[rg * 4 + 1][kb];
            float4 a2 = *(const float4*)&As[rg * 4 + 2][kb];
            float4 a3 = *(const float4*)&As[rg * 4 + 3][kb];
            float4 b0 = *(const float4*)&Bs[eg][kb];
            float4 b1 = *(const float4*)&Bs[eg + 32][kb];
            DOT4ACC(acc[0][0], a0, b0); DOT4ACC(acc[0][1], a0, b1);
            DOT4ACC(acc[1][0], a1, b0); DOT4ACC(acc[1][1], a1, b1);
            DOT4ACC(acc[2][0], a2, b0); DOT4ACC(acc[2][1], a2, b1);
            DOT4ACC(acc[3][0], a3, b0); DOT4ACC(acc[3][1], a3, b1);
        }

        #pragma unroll
        for (int r = 0; r < 4; r++) {
            const int grow = row0 + rg * 4 + r;
            #pragma unroll
            for (int q = 0; q < 2; q++) {
                const int e = e0 + c * 64 + eg + 32 * q;
                out[MERGE_OFF + (size_t)grow * Ee + e] =
                    bmask[r] * (acc[r][q] + proj_b[e]);
            }
        }
    }
}

// ---------------------------------------------------------------------------
extern "C" void kernel_launch(void* const* d_in, const int* in_sizes, int n_in,
                              void* d_out, int out_size)
{
    const float* pos     = (const float*)d_in[0];
    const float* means   = (const float*)d_in[1];
    const float* stds    = (const float*)d_in[2];
    const float* mul_w   = (const float*)d_in[3];
    const float* bias_w  = (const float*)d_in[4];
    const float* proj_w  = (const float*)d_in[5];
    const float* proj_b  = (const float*)d_in[6];
    const int*   nte     = (const int*)d_in[7];
    const void*  pad_mask  = d_in[8];
    const void*  node_mask = d_in[9];
    float* out = (float*)d_out;

    detect_masks<<<1, 128>>>((const unsigned int*)pad_mask,
                             (const unsigned int*)node_mask);
    edge_kernel<<<Bsz * Nn, 128>>>(pos, means, stds, mul_w, bias_w, nte,
                                   pad_mask, node_mask, out);
    merge_kernel<<<dim3(64, 2), 256>>>(proj_w, proj_b, pad_mask, node_mask, out);
}

// round 3
// speedup vs baseline: 1.1102x; 1.1102x over previous
#include <cuda_runtime.h>
#include <math.h>

// Problem shapes (fixed by the reference)
#define Bsz 4
#define Nn  512
#define Kk  128
#define Ee  768

static constexpr size_t EF_ELEMS    = (size_t)Bsz * Nn * Nn * Kk;   // 134,217,728
static constexpr size_t MERGE_ELEMS = (size_t)Bsz * Nn * Ee;        //   1,572,864
static constexpr size_t MERGE_OFF   = EF_ELEMS;
static constexpr size_t DP_OFF      = EF_ELEMS + MERGE_ELEMS;

// Scratch for sum over j of edge_feature: [B*N, K]  (1 MB, static device array)
__device__ float g_sum[(size_t)Bsz * Nn * Kk];

// ---------------------------------------------------------------------------
// Inline mask-dtype classification (0 = uint8, 1 = int32, 2 = float32).
// Every block computes the same result from the same 2048 bytes (L2-hot).
// int32 0/1 words -> high 3 bytes zero. float32 words in {0, 0x3F800000}.
// uint8 0/1 bytes produce nonzero unaligned bytes w.p. ~1.
// ---------------------------------------------------------------------------
template <int NT>
__device__ __forceinline__ void classify_masks(const unsigned int* __restrict__ pad,
                                               const unsigned int* __restrict__ node,
                                               int tid, int& mp, int& mn)
{
    __shared__ unsigned int s_hi[2], s_bad[2];
    if (tid < 2) { s_hi[tid] = 0u; s_bad[tid] = 0u; }
    __syncthreads();
    const unsigned int* bufs[2] = { pad, node };
    #pragma unroll
    for (int m = 0; m < 2; m++) {
        unsigned int h = 0u, bf = 0u;
        for (int w = tid; w < 512; w += NT) {      // 2048 bytes
            unsigned int v = bufs[m][w];
            h |= (v & 0xFFFFFF00u);
            if (v != 0u && v != 0x3F800000u) bf = 1u;
        }
        if (h)  atomicOr(&s_hi[m],  h);
        if (bf) atomicOr(&s_bad[m], 1u);
    }
    __syncthreads();
    mp = (s_hi[0] == 0u) ? 1 : (s_bad[0] == 0u ? 2 : 0);
    mn = (s_hi[1] == 0u) ? 1 : (s_bad[1] == 0u ? 2 : 0);
}

__device__ __forceinline__ bool mget(const void* p, int idx, int mode)
{
    if (mode == 1) return ((const int*)p)[idx] != 0;
    if (mode == 2) return ((const float*)p)[idx] != 0.0f;
    return ((const unsigned char*)p)[idx] != 0;
}

__device__ __forceinline__ float ex2f(float x)
{
    float r;
    asm("ex2.approx.ftz.f32 %0, %1;" : "=f"(r) : "f"(x));
    return r;
}

// ---------------------------------------------------------------------------
// Kernel 1: per (b,i) block. Computes delta_pos, edge_feature (streamed),
// and the j-reduction into g_sum.
// ---------------------------------------------------------------------------
__global__ __launch_bounds__(128) void edge_kernel(
    const float* __restrict__ pos,
    const float* __restrict__ means,
    const float* __restrict__ stds,
    const float* __restrict__ mul_w,
    const float* __restrict__ bias_w,
    const int*   __restrict__ nte,
    const void*  __restrict__ pad_mask,
    const void*  __restrict__ node_mask,
    float* __restrict__ out)
{
    const int bi  = blockIdx.x;       // b*512 + i
    const int b   = bi >> 9;
    const int tid = threadIdx.x;      // 0..127

    __shared__ float sx[Nn];          // x = mul*dist + bias per j
    __shared__ float spm[Nn];         // 0 if padding_mask[b,j] else 1
    __shared__ float red[4][Kk];      // cross-j_sub partial sums

    int mp, mn;
    classify_masks<128>((const unsigned int*)pad_mask,
                        (const unsigned int*)node_mask, tid, mp, mn);

    const float pix = pos[(size_t)bi * 3 + 0];
    const float piy = pos[(size_t)bi * 3 + 1];
    const float piz = pos[(size_t)bi * 3 + 2];
    const bool  nmi = mget(node_mask, bi, mn);

    // ---- Phase 1: per-j scalars + delta_pos output ----
    for (int j = tid; j < Nn; j += 128) {
        const size_t pj = ((size_t)b * Nn + j) * 3;
        float dx = pos[pj + 0] - pix;
        float dy = pos[pj + 1] - piy;
        float dz = pos[pj + 2] - piz;
        float d2 = dx * dx + dy * dy + dz * dz;
        float dist = (d2 > 0.0f) ? sqrtf(d2) : 0.0f;
        float inv  = 1.0f / (dist + 1e-5f);

        size_t dpo = DP_OFF + ((size_t)bi * Nn + j) * 3;
        out[dpo + 0] = dx * inv;
        out[dpo + 1] = dy * inv;
        out[dpo + 2] = dz * inv;

        size_t eo = ((size_t)bi * Nn + j) * 2;
        int et0 = nte[eo + 0];
        int et1 = nte[eo + 1];
        if (nmi)                             et0 = 0;
        if (mget(node_mask, b * Nn + j, mn)) et1 = 0;

        float mul  = mul_w[et0]  + mul_w[et1];
        float bias = bias_w[et0] + bias_w[et1];
        sx[j]  = fmaf(mul, dist, bias);
        spm[j] = mget(pad_mask, b * Nn + j, mp) ? 0.0f : 1.0f;
    }
    __syncthreads();

    // ---- Phase 2: gaussian basis, streamed stores, j-sum ----
    const int jsub = tid >> 5;            // 0..3
    const int k4   = (tid & 31) * 4;      // this thread's 4 k-values

    // aa = -0.5 * log2(e) / s^2, folded so exp is a single EX2.
    float mm[4], aa[4], cf[4];
    #pragma unroll
    for (int q = 0; q < 4; q++) {
        float s  = fabsf(stds[k4 + q]) + 0.01f;
        float is = 1.0f / s;
        aa[q] = -0.72134752f * is * is;
        mm[q] = means[k4 + q];
        cf[q] = 1.0f / (2.5066268f * s);  // 1/(sqrt(2*3.14159)*s)
    }

    float acc0 = 0.f, acc1 = 0.f, acc2 = 0.f, acc3 = 0.f;
    const size_t base = (size_t)bi * Nn * Kk;

    #pragma unroll 4
    for (int jb = 0; jb < Nn; jb += 4) {
        const int j = jb + jsub;
        const float x  = sx[j];    // broadcast within warp
        const float pm = spm[j];

        float p0 = pm * cf[0], p1 = pm * cf[1];
        float p2 = pm * cf[2], p3 = pm * cf[3];

        float d0 = x - mm[0], d1 = x - mm[1];
        float d2 = x - mm[2], d3 = x - mm[3];

        float4 v;
        v.x = p0 * ex2f(aa[0] * d0 * d0);
        v.y = p1 * ex2f(aa[1] * d1 * d1);
        v.z = p2 * ex2f(aa[2] * d2 * d2);
        v.w = p3 * ex2f(aa[3] * d3 * d3);

        acc0 += v.x; acc1 += v.y; acc2 += v.z; acc3 += v.w;

        // Streaming (evict-first) 16B coalesced store of edge_feature
        __stcs(reinterpret_cast<float4*>(out + base + (size_t)j * Kk + k4), v);
    }

    red[jsub][k4 + 0] = acc0;
    red[jsub][k4 + 1] = acc1;
    red[jsub][k4 + 2] = acc2;
    red[jsub][k4 + 3] = acc3;
    __syncthreads();

    // tid indexes k (blockDim == Kk == 128)
    {
        const int k = tid;
        float s = red[0][k] + red[1][k] + red[2][k] + red[3][k];
        g_sum[(size_t)bi * Kk + k] = s;
    }
}

// ---------------------------------------------------------------------------
// Kernel 2: merge = g_sum @ proj_w^T + proj_b, masked.
// M=2048, N=768, K=128. BM=32, BN=64, grid (64, 12) = 768 blocks.
// ---------------------------------------------------------------------------
#define DOT4ACC(accv, av, bv) \
    accv = fmaf((av).x, (bv).x, fmaf((av).y, (bv).y, fmaf((av).z, (bv).z, fmaf((av).w, (bv).w, accv))))

__global__ __launch_bounds__(256) void merge_kernel(
    const float* __restrict__ proj_w,
    const float* __restrict__ proj_b,
    const void* __restrict__ pad_mask,
    const void* __restrict__ node_mask,
    float* __restrict__ out)
{
    __shared__ float As[32][132];   // padded, 16B-aligned rows
    __shared__ float Bs[64][132];

    const int tid  = threadIdx.x;
    const int row0 = blockIdx.x * 32;   // 64 blocks in x
    const int e0   = blockIdx.y * 64;   // 12 blocks in y

    int mp, mn;
    classify_masks<256>((const unsigned int*)pad_mask,
                        (const unsigned int*)node_mask, tid, mp, mn);

    for (int idx = tid; idx < 32 * 128; idx += 256)
        As[idx >> 7][idx & 127] = g_sum[(size_t)row0 * 128 + idx];
    {
        const float* pw = proj_w + (size_t)e0 * 128;
        for (int idx = tid; idx < 64 * 128; idx += 256)
            Bs[idx >> 7][idx & 127] = pw[idx];
    }

    const int rg = tid >> 5;   // 0..7 -> rows rg*4 .. rg*4+3
    const int eg = tid & 31;   // e within chunk: eg and eg+32

    float bmask[4];
    #pragma unroll
    for (int r = 0; r < 4; r++) {
        int grow = row0 + rg * 4 + r;
        bmask[r] = (mget(pad_mask, grow, mp) || mget(node_mask, grow, mn))
                       ? 0.0f : 1.0f;
    }
    __syncthreads();

    float acc[4][2] = {};
    #pragma unroll
    for (int kb = 0; kb < 128; kb += 4) {
        float4 a0 = *(const float4*)&As[rg * 4 + 0][kb];
        float4 a1 = *(const float4*)&As[rg * 4 + 1][kb];
        float4 a2 = *(const float4*)&As[rg * 4 + 2][kb];
        float4 a3 = *(const float4*)&As[rg * 4 + 3][kb];
        float4 b0 = *(const float4*)&Bs[eg][kb];
        float4 b1 = *(const float4*)&Bs[eg + 32][kb];
        DOT4ACC(acc[0][0], a0, b0); DOT4ACC(acc[0][1], a0, b1);
        DOT4ACC(acc[1][0], a1, b0); DOT4ACC(acc[1][1], a1, b1);
        DOT4ACC(acc[2][0], a2, b0); DOT4ACC(acc[2][1], a2, b1);
        DOT4ACC(acc[3][0], a3, b0); DOT4ACC(acc[3][1], a3, b1);
    }

    #pragma unroll
    for (int r = 0; r < 4; r++) {
        const int grow = row0 + rg * 4 + r;
        #pragma unroll
        for (int q = 0; q < 2; q++) {
            const int e = e0 + eg + 32 * q;
            out[MERGE_OFF + (size_t)grow * Ee + e] =
                bmask[r] * (acc[r][q] + proj_b[e]);
        }
    }
}

// ---------------------------------------------------------------------------
extern "C" void kernel_launch(void* const* d_in, const int* in_sizes, int n_in,
                              void* d_out, int out_size)
{
    const float* pos     = (const float*)d_in[0];
    const float* means   = (const float*)d_in[1];
    const float* stds    = (const float*)d_in[2];
    const float* mul_w   = (const float*)d_in[3];
    const float* bias_w  = (const float*)d_in[4];
    const float* proj_w  = (const float*)d_in[5];
    const float* proj_b  = (const float*)d_in[6];
    const int*   nte     = (const int*)d_in[7];
    const void*  pad_mask  = d_in[8];
    const void*  node_mask = d_in[9];
    float* out = (float*)d_out;

    edge_kernel<<<Bsz * Nn, 128>>>(pos, means, stds, mul_w, bias_w, nte,
                                   pad_mask, node_mask, out);
    merge_kernel<<<dim3(64, 12), 256>>>(proj_w, proj_b, pad_mask, node_mask, out);
}

// round 4
// speedup vs baseline: 1.1545x; 1.0398x over previous
#include <cuda_runtime.h>
#include <math.h>

// Problem shapes (fixed by the reference)
#define Bsz 4
#define Nn  512
#define Kk  128
#define Ee  768

static constexpr size_t EF_ELEMS    = (size_t)Bsz * Nn * Nn * Kk;   // 134,217,728
static constexpr size_t MERGE_ELEMS = (size_t)Bsz * Nn * Ee;        //   1,572,864
static constexpr size_t MERGE_OFF   = EF_ELEMS;
static constexpr size_t DP_OFF      = EF_ELEMS + MERGE_ELEMS;

static constexpr int N_PROD  = Bsz * Nn;          // 2048 producer blocks
static constexpr int N_GROUP = N_PROD / 32;       // 64 row-groups of 32 rows
static constexpr int N_ECHNK = Ee / 64;           // 12 e-chunks of 64
static constexpr int N_CONS  = N_GROUP * N_ECHNK; // 768 consumer blocks

// Scratch: j-summed features [B*N, K] (1 MB) + handshake counters.
__device__ float g_sum[(size_t)N_PROD * Kk];
__device__ int   g_cnt[N_GROUP];    // producers done per row-group (self-resetting)
__device__ int   g_done[N_GROUP];   // consumers done per row-group (self-resetting)

// ---------------------------------------------------------------------------
// Inline mask-dtype classification (0 = uint8, 1 = int32, 2 = float32).
// ---------------------------------------------------------------------------
__device__ __forceinline__ void classify_masks(const unsigned int* __restrict__ pad,
                                               const unsigned int* __restrict__ node,
                                               int tid, int nt, int& mp, int& mn)
{
    __shared__ unsigned int s_hi[2], s_bad[2];
    if (tid < 2) { s_hi[tid] = 0u; s_bad[tid] = 0u; }
    __syncthreads();
    const unsigned int* bufs[2] = { pad, node };
    #pragma unroll
    for (int m = 0; m < 2; m++) {
        unsigned int h = 0u, bf = 0u;
        for (int w = tid; w < 512; w += nt) {      // 2048 bytes
            unsigned int v = bufs[m][w];
            h |= (v & 0xFFFFFF00u);
            if (v != 0u && v != 0x3F800000u) bf = 1u;
        }
        if (h)  atomicOr(&s_hi[m],  h);
        if (bf) atomicOr(&s_bad[m], 1u);
    }
    __syncthreads();
    mp = (s_hi[0] == 0u) ? 1 : (s_bad[0] == 0u ? 2 : 0);
    mn = (s_hi[1] == 0u) ? 1 : (s_bad[1] == 0u ? 2 : 0);
}

__device__ __forceinline__ bool mget(const void* p, int idx, int mode)
{
    if (mode == 1) return ((const int*)p)[idx] != 0;
    if (mode == 2) return ((const float*)p)[idx] != 0.0f;
    return ((const unsigned char*)p)[idx] != 0;
}

__device__ __forceinline__ float ex2f(float x)
{
    float r;
    asm("ex2.approx.ftz.f32 %0, %1;" : "=f"(r) : "f"(x));
    return r;
}

#define DOT4ACC(accv, av, bv) \
    accv = fmaf((av).x, (bv).x, fmaf((av).y, (bv).y, fmaf((av).z, (bv).z, fmaf((av).w, (bv).w, accv))))

// ---------------------------------------------------------------------------
// Fused kernel. bids [0,2048): producers (edge_feature + delta_pos + g_sum).
// bids [2048,2816): consumers (merge GEMM tiles, gated on g_cnt).
// ---------------------------------------------------------------------------
__global__ __launch_bounds__(256) void fused_kernel(
    const float* __restrict__ pos,
    const float* __restrict__ means,
    const float* __restrict__ stds,
    const float* __restrict__ mul_w,
    const float* __restrict__ bias_w,
    const int*   __restrict__ nte,
    const void*  __restrict__ pad_mask,
    const void*  __restrict__ node_mask,
    const float* __restrict__ proj_w,
    const float* __restrict__ proj_b,
    float* __restrict__ out)
{
    const int tid = threadIdx.x;   // 0..255

    if (blockIdx.x < N_PROD) {
        // ================= PRODUCER =================
        const int bi = blockIdx.x;       // b*512 + i
        const int b  = bi >> 9;

        __shared__ float sx[Nn];         // x = mul*dist + bias per j
        __shared__ float spm[Nn];        // 0 if padding_mask[b,j] else 1
        __shared__ float red[8][Kk];     // cross-jsub partial sums

        int mp, mn;
        classify_masks((const unsigned int*)pad_mask,
                       (const unsigned int*)node_mask, tid, 256, mp, mn);

        const float pix = pos[(size_t)bi * 3 + 0];
        const float piy = pos[(size_t)bi * 3 + 1];
        const float piz = pos[(size_t)bi * 3 + 2];
        const bool  nmi = mget(node_mask, bi, mn);

        // ---- Phase 1: per-j scalars + delta_pos output ----
        for (int j = tid; j < Nn; j += 256) {
            const size_t pj = ((size_t)b * Nn + j) * 3;
            float dx = pos[pj + 0] - pix;
            float dy = pos[pj + 1] - piy;
            float dz = pos[pj + 2] - piz;
            float d2 = dx * dx + dy * dy + dz * dz;
            float dist = (d2 > 0.0f) ? sqrtf(d2) : 0.0f;
            float inv  = 1.0f / (dist + 1e-5f);

            size_t dpo = DP_OFF + ((size_t)bi * Nn + j) * 3;
            out[dpo + 0] = dx * inv;
            out[dpo + 1] = dy * inv;
            out[dpo + 2] = dz * inv;

            size_t eo = ((size_t)bi * Nn + j) * 2;
            int et0 = nte[eo + 0];
            int et1 = nte[eo + 1];
            if (nmi)                             et0 = 0;
            if (mget(node_mask, b * Nn + j, mn)) et1 = 0;

            float mul  = mul_w[et0]  + mul_w[et1];
            float bias = bias_w[et0] + bias_w[et1];
            sx[j]  = fmaf(mul, dist, bias);
            spm[j] = mget(pad_mask, b * Nn + j, mp) ? 0.0f : 1.0f;
        }
        __syncthreads();

        // ---- Phase 2: gaussian basis, streamed stores, j-sum ----
        const int jsub = tid >> 5;            // 0..7
        const int k4   = (tid & 31) * 4;      // this thread's 4 k-values

        float mm[4], aa[4], cf[4];
        #pragma unroll
        for (int q = 0; q < 4; q++) {
            float s  = fabsf(stds[k4 + q]) + 0.01f;
            float is = 1.0f / s;
            aa[q] = -0.72134752f * is * is;     // -0.5*log2(e)/s^2
            mm[q] = means[k4 + q];
            cf[q] = 1.0f / (2.5066268f * s);    // 1/(sqrt(2*pi)*s)
        }

        float acc0 = 0.f, acc1 = 0.f, acc2 = 0.f, acc3 = 0.f;
        const size_t base = (size_t)bi * Nn * Kk;

        #pragma unroll 4
        for (int jb = 0; jb < Nn; jb += 8) {
            const int j = jb + jsub;
            const float x  = sx[j];
            const float pm = spm[j];

            float p0 = pm * cf[0], p1 = pm * cf[1];
            float p2 = pm * cf[2], p3 = pm * cf[3];
            float d0 = x - mm[0], d1 = x - mm[1];
            float d2 = x - mm[2], d3 = x - mm[3];

            float4 v;
            v.x = p0 * ex2f(aa[0] * d0 * d0);
            v.y = p1 * ex2f(aa[1] * d1 * d1);
            v.z = p2 * ex2f(aa[2] * d2 * d2);
            v.w = p3 * ex2f(aa[3] * d3 * d3);

            acc0 += v.x; acc1 += v.y; acc2 += v.z; acc3 += v.w;
            __stcs(reinterpret_cast<float4*>(out + base + (size_t)j * Kk + k4), v);
        }

        red[jsub][k4 + 0] = acc0;
        red[jsub][k4 + 1] = acc1;
        red[jsub][k4 + 2] = acc2;
        red[jsub][k4 + 3] = acc3;
        __syncthreads();

        if (tid < Kk) {
            float s = 0.f;
            #pragma unroll
            for (int r = 0; r < 8; r++) s += red[r][tid];
            g_sum[(size_t)bi * Kk + tid] = s;
        }
        __syncthreads();

        // Signal: this row of g_sum is complete.
        if (tid == 0) {
            __threadfence();
            atomicAdd(&g_cnt[bi >> 5], 1);
        }
    } else {
        // ================= CONSUMER (merge tile) =================
        const int cid = blockIdx.x - N_PROD;   // 0..767
        const int g   = cid / N_ECHNK;         // row-group 0..63
        const int ec  = cid % N_ECHNK;         // e-chunk 0..11
        const int row0 = g * 32;
        const int e0   = ec * 64;

        __shared__ float As[32][132];
        __shared__ float Bs[64][132];

        int mp, mn;
        classify_masks((const unsigned int*)pad_mask,
                       (const unsigned int*)node_mask, tid, 256, mp, mn);

        // Load B tile while waiting is still possible (independent of g_sum).
        {
            const float* pw = proj_w + (size_t)e0 * 128;
            for (int idx = tid; idx < 64 * 128; idx += 256)
                Bs[idx >> 7][idx & 127] = pw[idx];
        }

        const int rg = tid >> 5;   // 0..7 -> rows rg*4 .. rg*4+3
        const int eg = tid & 31;

        float bmask[4];
        #pragma unroll
        for (int r = 0; r < 4; r++) {
            int grow = row0 + rg * 4 + r;
            bmask[r] = (mget(pad_mask, grow, mp) || mget(node_mask, grow, mn))
                           ? 0.0f : 1.0f;
        }

        // Wait until all 32 producer rows of this group are published.
        if (tid == 0) {
            while (atomicAdd(&g_cnt[g], 0) < 32) __nanosleep(200);
        }
        __syncthreads();
        __threadfence();   // acquire: order g_sum reads after observed count

        for (int idx = tid; idx < 32 * 128; idx += 256)
            As[idx >> 7][idx & 127] = g_sum[(size_t)row0 * 128 + idx];
        __syncthreads();

        float acc[4][2] = {};
        #pragma unroll
        for (int kb = 0; kb < 128; kb += 4) {
            float4 a0 = *(const float4*)&As[rg * 4 + 0][kb];
            float4 a1 = *(const float4*)&As[rg * 4 + 1][kb];
            float4 a2 = *(const float4*)&As[rg * 4 + 2][kb];
            float4 a3 = *(const float4*)&As[rg * 4 + 3][kb];
            float4 b0 = *(const float4*)&Bs[eg][kb];
            float4 b1 = *(const float4*)&Bs[eg + 32][kb];
            DOT4ACC(acc[0][0], a0, b0); DOT4ACC(acc[0][1], a0, b1);
            DOT4ACC(acc[1][0], a1, b0); DOT4ACC(acc[1][1], a1, b1);
            DOT4ACC(acc[2][0], a2, b0); DOT4ACC(acc[2][1], a2, b1);
            DOT4ACC(acc[3][0], a3, b0); DOT4ACC(acc[3][1], a3, b1);
        }

        #pragma unroll
        for (int r = 0; r < 4; r++) {
            const int grow = row0 + rg * 4 + r;
            #pragma unroll
            for (int q = 0; q < 2; q++) {
                const int e = e0 + eg + 32 * q;
                out[MERGE_OFF + (size_t)grow * Ee + e] =
                    bmask[r] * (acc[r][q] + proj_b[e]);
            }
        }

        // Last consumer of this group resets counters for the next replay.
        __syncthreads();
        if (tid == 0) {
            int d = atomicAdd(&g_done[g], 1);
            if (d == N_ECHNK - 1) {
                g_cnt[g]  = 0;
                g_done[g] = 0;
                __threadfence();
            }
        }
    }
}

// ---------------------------------------------------------------------------
extern "C" void kernel_launch(void* const* d_in, const int* in_sizes, int n_in,
                              void* d_out, int out_size)
{
    const float* pos     = (const float*)d_in[0];
    const float* means   = (const float*)d_in[1];
    const float* stds    = (const float*)d_in[2];
    const float* mul_w   = (const float*)d_in[3];
    const float* bias_w  = (const float*)d_in[4];
    const float* proj_w  = (const float*)d_in[5];
    const float* proj_b  = (const float*)d_in[6];
    const int*   nte     = (const int*)d_in[7];
    const void*  pad_mask  = d_in[8];
    const void*  node_mask = d_in[9];
    float* out = (float*)d_out;

    fused_kernel<<<N_PROD + N_CONS, 256>>>(pos, means, stds, mul_w, bias_w, nte,
                                           pad_mask, node_mask, proj_w, proj_b, out);
}